// round 10
// baseline (speedup 1.0000x reference)
#include <cuda_runtime.h>
#include <cuda_bf16.h>
#include <cuda_fp16.h>
#include <cstdint>
#include <cstddef>

// ===========================================================================
// RelativeAttention on sm_100 (plain target: legacy mma.sync / HMMA).
// R10: Q scaled x1024 (kills fp16-subnormal FTZ of Qlo), 3-stage single-sync
//      mainloops for SIM/OUT, den-zero fused into l2norm.
//
//   1) split x, anchors -> bf16 hi/lo; transpose+split Wq, Wk; values -> Vt fp16
//   2) Qf = x @ Wq, Kf = anchors @ Wk    (3-term bf16 mma, fp32 store)
//   3) l2norm rows: Q -> fp16 hi/lo of 1024*qhat (+den=0), K -> fp16
//   4) SIM (2-term fp16): acc*2^-10 -> quant->exp -> E fp16 + rowsum atomics
//   5) OUT (1-term fp16): O = E @ Vt^T -> scale 1/den -> fp32 out
// ===========================================================================

// ------------------------- device scratch ----------------------------------
__device__ float g_Qf[16384 * 512];
__device__ float g_Kf[4096 * 512];
__device__ float g_den[16384];
__device__ __nv_bfloat16 g_xhi[16384 * 512];
__device__ __nv_bfloat16 g_xlo[16384 * 512];
__device__ __nv_bfloat16 g_ahi[4096 * 512];
__device__ __nv_bfloat16 g_alo[4096 * 512];
__device__ __nv_bfloat16 g_Wqthi[512 * 512];
__device__ __nv_bfloat16 g_Wqtlo[512 * 512];
__device__ __nv_bfloat16 g_Wkthi[512 * 512];
__device__ __nv_bfloat16 g_Wktlo[512 * 512];
__device__ __half g_Qhi[16384 * 512];
__device__ __half g_Qlo[16384 * 512];
__device__ __half g_Kh[4096 * 512];
__device__ __half g_E[(size_t)16384 * 4096];
__device__ __half g_Vt[512 * 4096];

// ------------------------- helpers -----------------------------------------
__device__ __forceinline__ uint32_t s2u(const void* p) {
    uint32_t a;
    asm("{ .reg .u64 t; cvta.to.shared.u64 t, %1; cvt.u32.u64 %0, t; }"
        : "=r"(a) : "l"(p));
    return a;
}

__device__ __forceinline__ void cp16(uint32_t dst, const void* src) {
    asm volatile("cp.async.cg.shared.global [%0], [%1], 16;" :: "r"(dst), "l"(src));
}
#define CP_COMMIT() asm volatile("cp.async.commit_group;" ::: "memory")
#define CP_WAIT1()  asm volatile("cp.async.wait_group 1;" ::: "memory")

__device__ __forceinline__ void ldsm4(uint32_t* r, uint32_t addr) {
    asm volatile("ldmatrix.sync.aligned.m8n8.x4.shared.b16 {%0,%1,%2,%3}, [%4];"
        : "=r"(r[0]), "=r"(r[1]), "=r"(r[2]), "=r"(r[3]) : "r"(addr));
}

__device__ __forceinline__ void mma_bf16(float* d, const uint32_t* a, const uint32_t* b) {
    asm volatile(
        "mma.sync.aligned.m16n8k16.row.col.f32.bf16.bf16.f32 "
        "{%0,%1,%2,%3}, {%4,%5,%6,%7}, {%8,%9}, {%0,%1,%2,%3};"
        : "+f"(d[0]), "+f"(d[1]), "+f"(d[2]), "+f"(d[3])
        : "r"(a[0]), "r"(a[1]), "r"(a[2]), "r"(a[3]), "r"(b[0]), "r"(b[1]));
}

__device__ __forceinline__ void mma_f16(float* d, const uint32_t* a, const uint32_t* b) {
    asm volatile(
        "mma.sync.aligned.m16n8k16.row.col.f32.f16.f16.f32 "
        "{%0,%1,%2,%3}, {%4,%5,%6,%7}, {%8,%9}, {%0,%1,%2,%3};"
        : "+f"(d[0]), "+f"(d[1]), "+f"(d[2]), "+f"(d[3])
        : "r"(a[0]), "r"(a[1]), "r"(a[2]), "r"(a[3]), "r"(b[0]), "r"(b[1]));
}

__device__ __forceinline__ uint32_t pack_bf2(float a, float b) {
    __nv_bfloat16 ha = __float2bfloat16(a), hb = __float2bfloat16(b);
    return (uint32_t)__bfloat16_as_ushort(ha) |
           ((uint32_t)__bfloat16_as_ushort(hb) << 16);
}
__device__ __forceinline__ uint32_t pack_h2(float a, float b) {
    __half2 h = __floats2half2_rn(a, b);
    return *(uint32_t*)&h;
}

// ------------------------- tiling constants ---------------------------------
#define ROWB 80
#define TILEB (128 * ROWB)              // 10240 per tile
#define STAGE4 (4 * TILEB)              // proj: Ahi,Alo,Bhi,Blo (2-stage)
#define STAGE3T (3 * TILEB)             // sim:  Ahi,Alo,B       (3-stage)
#define STAGE2T (2 * TILEB)             // out:  A,B             (3-stage)
static constexpr int SMEM4  = 2 * STAGE4;    // 81920
static constexpr int SMEM3T = 3 * STAGE3T;   // 92160
static constexpr int SMEM2T = 3 * STAGE2T;   // 61440

// ------------------------- stage loaders ------------------------------------
__device__ __forceinline__ void load_stage4(
    uint32_t sbase, const __nv_bfloat16* Ahi, const __nv_bfloat16* Alo,
    const __nv_bfloat16* Bhi, const __nv_bfloat16* Blo,
    int bm0, int bn0, int K, int c, int tid)
{
    const __nv_bfloat16* gp[4] = { Ahi, Alo, Bhi, Blo };
    const int rb[4] = { bm0, bm0, bn0, bn0 };
    const size_t kb = (size_t)c * 32;
#pragma unroll
    for (int t = 0; t < 8; t++) {
        const int seg  = tid + t * 256;
        const int tile = seg >> 9;
        const int w    = seg & 511;
        const int row  = w >> 2;
        const int c16  = w & 3;
        const __nv_bfloat16* src = gp[tile] + (size_t)(rb[tile] + row) * K + kb + c16 * 8;
        cp16(sbase + tile * TILEB + row * ROWB + c16 * 16, src);
    }
}

__device__ __forceinline__ void load_stage3(
    uint32_t sbase, const __half* Ahi, const __half* Alo, const __half* B,
    int bm0, int bn0, int K, int c, int tid)
{
    const __half* gp[3] = { Ahi, Alo, B };
    const int rb[3] = { bm0, bm0, bn0 };
    const size_t kb = (size_t)c * 32;
#pragma unroll
    for (int t = 0; t < 6; t++) {
        const int seg  = tid + t * 256;
        const int tile = seg >> 9;
        const int w    = seg & 511;
        const int row  = w >> 2;
        const int c16  = w & 3;
        const __half* src = gp[tile] + (size_t)(rb[tile] + row) * K + kb + c16 * 8;
        cp16(sbase + tile * TILEB + row * ROWB + c16 * 16, src);
    }
}

__device__ __forceinline__ void load_stage2(
    uint32_t sbase, const __half* A, const __half* B,
    int bm0, int bn0, int K, int c, int tid)
{
    const __half* gp[2] = { A, B };
    const int rb[2] = { bm0, bn0 };
    const size_t kb = (size_t)c * 32;
#pragma unroll
    for (int t = 0; t < 4; t++) {
        const int seg  = tid + t * 256;
        const int tile = seg >> 9;
        const int w    = seg & 511;
        const int row  = w >> 2;
        const int c16  = w & 3;
        const __half* src = gp[tile] + (size_t)(rb[tile] + row) * K + kb + c16 * 8;
        cp16(sbase + tile * TILEB + row * ROWB + c16 * 16, src);
    }
}

// ------------------------- 3-term bf16 projection GEMM ----------------------
__global__ __launch_bounds__(256, 2)
void proj3_kernel(const __nv_bfloat16* __restrict__ Ahi,
                  const __nv_bfloat16* __restrict__ Alo,
                  const __nv_bfloat16* __restrict__ Bhi,
                  const __nv_bfloat16* __restrict__ Blo,
                  int K, int ldC,
                  float* __restrict__ Cf)
{
    extern __shared__ char sm[];
    const uint32_t sb = s2u(sm);
    const int tid  = threadIdx.x;
    const int wid  = tid >> 5;
    const int lane = tid & 31;
    const int wm   = wid >> 1;
    const int wn   = wid & 1;
    const int g    = lane >> 2;
    const int tg   = lane & 3;
    const int bm0  = blockIdx.y * 128;
    const int bn0  = blockIdx.x * 128;

    const int grp  = lane >> 3;
    const int lrow = lane & 7;
    const uint32_t a_off = (uint32_t)((wm * 32 + lrow + ((grp & 1) << 3)) * ROWB
                                      + ((grp >> 1) << 4));
    const uint32_t b_off = (uint32_t)((wn * 64 + lrow + ((grp >> 1) << 3)) * ROWB
                                      + ((grp & 1) << 4));

    float acc[2][8][4];
#pragma unroll
    for (int mt = 0; mt < 2; mt++)
#pragma unroll
        for (int nt = 0; nt < 8; nt++)
#pragma unroll
            for (int j = 0; j < 4; j++) acc[mt][nt][j] = 0.f;

    const int nch = K >> 5;
    load_stage4(sb,          Ahi, Alo, Bhi, Blo, bm0, bn0, K, 0, tid);
    CP_COMMIT();
    load_stage4(sb + STAGE4, Ahi, Alo, Bhi, Blo, bm0, bn0, K, 1, tid);
    CP_COMMIT();

    for (int c = 0; c < nch; c++) {
        CP_WAIT1();
        __syncthreads();
        const uint32_t st = sb + (c & 1) * STAGE4;

#pragma unroll
        for (int ks = 0; ks < 2; ks++) {
            const uint32_t kk = ks * 32;
            uint32_t ah[2][4], al[2][4], bh[4][4], bl[4][4];
#pragma unroll
            for (int mt = 0; mt < 2; mt++) {
                ldsm4(ah[mt], st + a_off + mt * (16 * ROWB) + kk);
                ldsm4(al[mt], st + TILEB + a_off + mt * (16 * ROWB) + kk);
            }
#pragma unroll
            for (int np = 0; np < 4; np++) {
                ldsm4(bh[np], st + 2 * TILEB + b_off + np * (16 * ROWB) + kk);
                ldsm4(bl[np], st + 3 * TILEB + b_off + np * (16 * ROWB) + kk);
            }
#pragma unroll
            for (int np = 0; np < 4; np++)
#pragma unroll
                for (int sub = 0; sub < 2; sub++)
#pragma unroll
                    for (int mt = 0; mt < 2; mt++) {
                        mma_bf16(acc[mt][np * 2 + sub], ah[mt], &bh[np][2 * sub]);
                        mma_bf16(acc[mt][np * 2 + sub], ah[mt], &bl[np][2 * sub]);
                        mma_bf16(acc[mt][np * 2 + sub], al[mt], &bh[np][2 * sub]);
                    }
        }
        __syncthreads();
        if (c + 2 < nch)
            load_stage4(sb + (c & 1) * STAGE4, Ahi, Alo, Bhi, Blo, bm0, bn0, K, c + 2, tid);
        CP_COMMIT();
    }

#pragma unroll
    for (int mt = 0; mt < 2; mt++) {
        const int rh = bm0 + wm * 32 + mt * 16 + g;
        const int rl = rh + 8;
#pragma unroll
        for (int nt = 0; nt < 8; nt++) {
            const int col = bn0 + wn * 64 + nt * 8 + tg * 2;
            *(float2*)(Cf + (size_t)rh * ldC + col) =
                make_float2(acc[mt][nt][0], acc[mt][nt][1]);
            *(float2*)(Cf + (size_t)rl * ldC + col) =
                make_float2(acc[mt][nt][2], acc[mt][nt][3]);
        }
    }
}

// ------------------------- 2-term fp16 SIM kernel (3-stage) -----------------
// S*1024 = Ahi@B^T + Alo@B^T; epilogue: *2^-10 -> quant->exp -> E + rowsum.
__global__ __launch_bounds__(256, 2)
void sim2_kernel(const __half* __restrict__ Ahi,
                 const __half* __restrict__ Alo,
                 const __half* __restrict__ Bk,
                 int K, int ldC,
                 float* __restrict__ den,
                 __half* __restrict__ E)
{
    extern __shared__ char sm[];
    const uint32_t sb = s2u(sm);
    const int tid  = threadIdx.x;
    const int wid  = tid >> 5;
    const int lane = tid & 31;
    const int wm   = wid >> 1;
    const int wn   = wid & 1;
    const int g    = lane >> 2;
    const int tg   = lane & 3;
    const int bm0  = blockIdx.y * 128;
    const int bn0  = blockIdx.x * 128;

    const int grp  = lane >> 3;
    const int lrow = lane & 7;
    const uint32_t a_off = (uint32_t)((wm * 32 + lrow + ((grp & 1) << 3)) * ROWB
                                      + ((grp >> 1) << 4));
    const uint32_t b_off = (uint32_t)((wn * 64 + lrow + ((grp >> 1) << 3)) * ROWB
                                      + ((grp & 1) << 4));

    float acc[2][8][4];
#pragma unroll
    for (int mt = 0; mt < 2; mt++)
#pragma unroll
        for (int nt = 0; nt < 8; nt++)
#pragma unroll
            for (int j = 0; j < 4; j++) acc[mt][nt][j] = 0.f;

    const int nch = K >> 5;   // 16
    load_stage3(sb,           Ahi, Alo, Bk, bm0, bn0, K, 0, tid);
    CP_COMMIT();
    load_stage3(sb + STAGE3T, Ahi, Alo, Bk, bm0, bn0, K, 1, tid);
    CP_COMMIT();

    int stg = 0;                       // stage of chunk c
    int wstg = 2;                      // stage to write chunk c+2 into
    for (int c = 0; c < nch; c++) {
        CP_WAIT1();
        __syncthreads();
        // prefetch chunk c+2 into the stage read at iteration c-1 (safe: all
        // warps finished reading it before the barrier above)
        if (c + 2 < nch)
            load_stage3(sb + wstg * STAGE3T, Ahi, Alo, Bk, bm0, bn0, K, c + 2, tid);
        CP_COMMIT();

        const uint32_t st = sb + stg * STAGE3T;
#pragma unroll
        for (int ks = 0; ks < 2; ks++) {
            const uint32_t kk = ks * 32;
            uint32_t ah[2][4], al[2][4], bh[4][4];
#pragma unroll
            for (int mt = 0; mt < 2; mt++) {
                ldsm4(ah[mt], st + a_off + mt * (16 * ROWB) + kk);
                ldsm4(al[mt], st + TILEB + a_off + mt * (16 * ROWB) + kk);
            }
#pragma unroll
            for (int np = 0; np < 4; np++)
                ldsm4(bh[np], st + 2 * TILEB + b_off + np * (16 * ROWB) + kk);
#pragma unroll
            for (int np = 0; np < 4; np++)
#pragma unroll
                for (int sub = 0; sub < 2; sub++)
#pragma unroll
                    for (int mt = 0; mt < 2; mt++)
                        mma_f16(acc[mt][np * 2 + sub], ah[mt], &bh[np][2 * sub]);
#pragma unroll
            for (int np = 0; np < 4; np++)
#pragma unroll
                for (int sub = 0; sub < 2; sub++)
#pragma unroll
                    for (int mt = 0; mt < 2; mt++)
                        mma_f16(acc[mt][np * 2 + sub], al[mt], &bh[np][2 * sub]);
        }
        stg  = (stg  == 2) ? 0 : stg + 1;
        wstg = (wstg == 2) ? 0 : wstg + 1;
    }

    // epilogue: undo the x1024 Q scaling (exact), quantize -> exp -> E + den
    const float inv = 9.765625e-4f;  // 2^-10
    float rs[2][2] = { {0.f, 0.f}, {0.f, 0.f} };
#pragma unroll
    for (int mt = 0; mt < 2; mt++) {
        const int rh = bm0 + wm * 32 + mt * 16 + g;
        const int rl = rh + 8;
#pragma unroll
        for (int nt = 0; nt < 8; nt++) {
            const int col = bn0 + wn * 64 + nt * 8 + tg * 2;
            float e0 = __expf(rintf((acc[mt][nt][0] * inv) / 0.05f) * 0.05f);
            float e1 = __expf(rintf((acc[mt][nt][1] * inv) / 0.05f) * 0.05f);
            float e2 = __expf(rintf((acc[mt][nt][2] * inv) / 0.05f) * 0.05f);
            float e3 = __expf(rintf((acc[mt][nt][3] * inv) / 0.05f) * 0.05f);
            rs[mt][0] += e0 + e1;
            rs[mt][1] += e2 + e3;
            *(uint32_t*)(E + (size_t)rh * ldC + col) = pack_h2(e0, e1);
            *(uint32_t*)(E + (size_t)rl * ldC + col) = pack_h2(e2, e3);
        }
    }
#pragma unroll
    for (int mt = 0; mt < 2; mt++)
#pragma unroll
        for (int hl = 0; hl < 2; hl++) {
            float v = rs[mt][hl];
            v += __shfl_xor_sync(0xffffffffu, v, 1);
            v += __shfl_xor_sync(0xffffffffu, v, 2);
            if (tg == 0)
                atomicAdd(&den[bm0 + wm * 32 + mt * 16 + g + hl * 8], v);
        }
}

// ------------------------- 1-term fp16 OUT kernel (3-stage) -----------------
__global__ __launch_bounds__(256, 2)
void out1_kernel(const __half* __restrict__ E,
                 const __half* __restrict__ Vt,
                 int K, int ldC,
                 const float* __restrict__ den,
                 float* __restrict__ Cf)
{
    extern __shared__ char sm[];
    const uint32_t sb = s2u(sm);
    const int tid  = threadIdx.x;
    const int wid  = tid >> 5;
    const int lane = tid & 31;
    const int wm   = wid >> 1;
    const int wn   = wid & 1;
    const int g    = lane >> 2;
    const int tg   = lane & 3;
    const int bm0  = blockIdx.y * 128;
    const int bn0  = blockIdx.x * 128;

    const int grp  = lane >> 3;
    const int lrow = lane & 7;
    const uint32_t a_off = (uint32_t)((wm * 32 + lrow + ((grp & 1) << 3)) * ROWB
                                      + ((grp >> 1) << 4));
    const uint32_t b_off = (uint32_t)((wn * 64 + lrow + ((grp >> 1) << 3)) * ROWB
                                      + ((grp & 1) << 4));

    float acc[2][8][4];
#pragma unroll
    for (int mt = 0; mt < 2; mt++)
#pragma unroll
        for (int nt = 0; nt < 8; nt++)
#pragma unroll
            for (int j = 0; j < 4; j++) acc[mt][nt][j] = 0.f;

    const int nch = K >> 5;   // 128
    load_stage2(sb,           E, Vt, bm0, bn0, K, 0, tid);
    CP_COMMIT();
    load_stage2(sb + STAGE2T, E, Vt, bm0, bn0, K, 1, tid);
    CP_COMMIT();

    int stg = 0, wstg = 2;
    for (int c = 0; c < nch; c++) {
        CP_WAIT1();
        __syncthreads();
        if (c + 2 < nch)
            load_stage2(sb + wstg * STAGE2T, E, Vt, bm0, bn0, K, c + 2, tid);
        CP_COMMIT();

        const uint32_t st = sb + stg * STAGE2T;
#pragma unroll
        for (int ks = 0; ks < 2; ks++) {
            const uint32_t kk = ks * 32;
            uint32_t ah[2][4], bh[4][4];
#pragma unroll
            for (int mt = 0; mt < 2; mt++)
                ldsm4(ah[mt], st + a_off + mt * (16 * ROWB) + kk);
#pragma unroll
            for (int np = 0; np < 4; np++)
                ldsm4(bh[np], st + TILEB + b_off + np * (16 * ROWB) + kk);
#pragma unroll
            for (int np = 0; np < 4; np++)
#pragma unroll
                for (int sub = 0; sub < 2; sub++)
#pragma unroll
                    for (int mt = 0; mt < 2; mt++)
                        mma_f16(acc[mt][np * 2 + sub], ah[mt], &bh[np][2 * sub]);
        }
        stg  = (stg  == 2) ? 0 : stg + 1;
        wstg = (wstg == 2) ? 0 : wstg + 1;
    }

#pragma unroll
    for (int mt = 0; mt < 2; mt++) {
        const int rh = bm0 + wm * 32 + mt * 16 + g;
        const int rl = rh + 8;
        const float sh = 1.0f / den[rh];
        const float sl = 1.0f / den[rl];
#pragma unroll
        for (int nt = 0; nt < 8; nt++) {
            const int col = bn0 + wn * 64 + nt * 8 + tg * 2;
            *(float2*)(Cf + (size_t)rh * ldC + col) =
                make_float2(acc[mt][nt][0] * sh, acc[mt][nt][1] * sh);
            *(float2*)(Cf + (size_t)rl * ldC + col) =
                make_float2(acc[mt][nt][2] * sl, acc[mt][nt][3] * sl);
        }
    }
}

// ------------------------- split fp32 -> bf16 hi/lo -------------------------
__global__ void split_kernel(const float* __restrict__ s,
                             __nv_bfloat16* __restrict__ hi,
                             __nv_bfloat16* __restrict__ lo, int n4)
{
    const int i = blockIdx.x * blockDim.x + threadIdx.x;
    if (i >= n4) return;
    float4 v = ((const float4*)s)[i];
    const float f[4] = { v.x, v.y, v.z, v.w };
    uint32_t hp[2], lp[2];
#pragma unroll
    for (int j = 0; j < 2; j++) {
        __nv_bfloat16 h0 = __float2bfloat16(f[2 * j]);
        __nv_bfloat16 h1 = __float2bfloat16(f[2 * j + 1]);
        hp[j] = (uint32_t)__bfloat16_as_ushort(h0) |
                ((uint32_t)__bfloat16_as_ushort(h1) << 16);
        lp[j] = pack_bf2(f[2 * j]     - __bfloat162float(h0),
                         f[2 * j + 1] - __bfloat162float(h1));
    }
    *(uint2*)(hi + (size_t)i * 4) = make_uint2(hp[0], hp[1]);
    *(uint2*)(lo + (size_t)i * 4) = make_uint2(lp[0], lp[1]);
}

// ----------------- transpose + split: src[R,C] -> out[C,R] bf16 hi/lo -------
__global__ void trans_split_kernel(const float* __restrict__ src,
                                   __nv_bfloat16* __restrict__ hi,
                                   __nv_bfloat16* __restrict__ lo,
                                   int R, int C)
{
    __shared__ float t[32][33];
    const int c0 = blockIdx.x * 32, r0 = blockIdx.y * 32;
    const int tx = threadIdx.x, ty = threadIdx.y;   // 32 x 8
#pragma unroll
    for (int j = 0; j < 32; j += 8)
        t[ty + j][tx] = src[(size_t)(r0 + ty + j) * C + c0 + tx];
    __syncthreads();
#pragma unroll
    for (int j = 0; j < 32; j += 8) {
        const float v = t[tx][ty + j];
        __nv_bfloat16 h = __float2bfloat16(v);
        const size_t o = (size_t)(c0 + ty + j) * R + r0 + tx;
        hi[o] = h;
        lo[o] = __float2bfloat16(v - __bfloat162float(h));
    }
}

// ----------------- transpose: src[R,C] fp32 -> out[C,R] fp16 ----------------
__global__ void trans_half_kernel(const float* __restrict__ src,
                                  __half* __restrict__ dst,
                                  int R, int C)
{
    __shared__ float t[32][33];
    const int c0 = blockIdx.x * 32, r0 = blockIdx.y * 32;
    const int tx = threadIdx.x, ty = threadIdx.y;   // 32 x 8
#pragma unroll
    for (int j = 0; j < 32; j += 8)
        t[ty + j][tx] = src[(size_t)(r0 + ty + j) * C + c0 + tx];
    __syncthreads();
#pragma unroll
    for (int j = 0; j < 32; j += 8)
        dst[(size_t)(c0 + ty + j) * R + r0 + tx] = __float2half_rn(t[tx][ty + j]);
}

// ------------------------- l2 normalize variants ----------------------------
// Q: fp16 hi/lo of 1024*qhat (residual well inside fp16 normal range);
//    also zeroes den[row].  K: single fp16 of khat.
__global__ void l2norm_split_h_kernel(const float* __restrict__ P,
                                      __half* __restrict__ hi,
                                      __half* __restrict__ lo,
                                      float* __restrict__ den)
{
    const int r = blockIdx.x;
    const int t = threadIdx.x;  // 128 threads x float4 (H=512)
    const float4 v = ((const float4*)(P + (size_t)r * 512))[t];
    float ss = v.x * v.x + v.y * v.y + v.z * v.z + v.w * v.w;
#pragma unroll
    for (int m = 16; m; m >>= 1) ss += __shfl_xor_sync(0xffffffffu, ss, m);
    __shared__ float ws[4];
    if ((t & 31) == 0) ws[t >> 5] = ss;
    __syncthreads();
    const float d = fmaxf(sqrtf(ws[0] + ws[1] + ws[2] + ws[3]), 1e-12f);
    const float s = 1024.0f / d;
    const float f[4] = { v.x * s, v.y * s, v.z * s, v.w * s };
    uint32_t hp[2], lp[2];
#pragma unroll
    for (int j = 0; j < 2; j++) {
        const float a = f[2 * j], b = f[2 * j + 1];
        __half h0 = __float2half_rn(a), h1 = __float2half_rn(b);
        __half2 hh; hh.x = h0; hh.y = h1;
        hp[j] = *(uint32_t*)&hh;
        lp[j] = pack_h2(a - __half2float(h0), b - __half2float(h1));
    }
    const size_t off = (size_t)r * 512 + t * 4;
    *(uint2*)(hi + off) = make_uint2(hp[0], hp[1]);
    *(uint2*)(lo + off) = make_uint2(lp[0], lp[1]);
    if (t == 0) den[r] = 0.f;
}

__global__ void l2norm_h_kernel(const float* __restrict__ P,
                                __half* __restrict__ dst)
{
    const int r = blockIdx.x;
    const int t = threadIdx.x;
    const float4 v = ((const float4*)(P + (size_t)r * 512))[t];
    float ss = v.x * v.x + v.y * v.y + v.z * v.z + v.w * v.w;
#pragma unroll
    for (int m = 16; m; m >>= 1) ss += __shfl_xor_sync(0xffffffffu, ss, m);
    __shared__ float ws[4];
    if ((t & 31) == 0) ws[t >> 5] = ss;
    __syncthreads();
    const float d = fmaxf(sqrtf(ws[0] + ws[1] + ws[2] + ws[3]), 1e-12f);
    uint32_t hp[2];
    hp[0] = pack_h2(v.x / d, v.y / d);
    hp[1] = pack_h2(v.z / d, v.w / d);
    *(uint2*)(dst + (size_t)r * 512 + t * 4) = make_uint2(hp[0], hp[1]);
}

// ------------------------- launch -------------------------------------------
extern "C" void kernel_launch(void* const* d_in, const int* in_sizes, int n_in,
                              void* d_out, int out_size)
{
    const float* x       = (const float*)d_in[0];
    const float* anchors = (const float*)d_in[1];
    const float* Wq      = (const float*)d_in[2];
    const float* Wk      = (const float*)d_in[3];
    const float* values  = (const float*)d_in[4];
    float* out = (float*)d_out;

    const int D = 512, H = 512;
    const int B = in_sizes[0] / D;   // 16384
    const int A = in_sizes[1] / D;   // 4096

    float *Qf, *Kf, *dn;
    __nv_bfloat16 *xhi, *xlo, *ahi, *alo, *Wqthi, *Wqtlo, *Wkthi, *Wktlo;
    __half *Qhi, *Qlo, *Kh, *E, *Vt;
    cudaGetSymbolAddress((void**)&Qf,    g_Qf);
    cudaGetSymbolAddress((void**)&Kf,    g_Kf);
    cudaGetSymbolAddress((void**)&dn,    g_den);
    cudaGetSymbolAddress((void**)&xhi,   g_xhi);
    cudaGetSymbolAddress((void**)&xlo,   g_xlo);
    cudaGetSymbolAddress((void**)&ahi,   g_ahi);
    cudaGetSymbolAddress((void**)&alo,   g_alo);
    cudaGetSymbolAddress((void**)&Wqthi, g_Wqthi);
    cudaGetSymbolAddress((void**)&Wqtlo, g_Wqtlo);
    cudaGetSymbolAddress((void**)&Wkthi, g_Wkthi);
    cudaGetSymbolAddress((void**)&Wktlo, g_Wktlo);
    cudaGetSymbolAddress((void**)&Qhi,   g_Qhi);
    cudaGetSymbolAddress((void**)&Qlo,   g_Qlo);
    cudaGetSymbolAddress((void**)&Kh,    g_Kh);
    cudaGetSymbolAddress((void**)&E,     g_E);
    cudaGetSymbolAddress((void**)&Vt,    g_Vt);

    cudaFuncSetAttribute(proj3_kernel,
                         cudaFuncAttributeMaxDynamicSharedMemorySize, SMEM4);
    cudaFuncSetAttribute(sim2_kernel,
                         cudaFuncAttributeMaxDynamicSharedMemorySize, SMEM3T);
    cudaFuncSetAttribute(out1_kernel,
                         cudaFuncAttributeMaxDynamicSharedMemorySize, SMEM2T);

    // 1) splits / transposes
    split_kernel<<<(B * D / 4 + 255) / 256, 256>>>(x, xhi, xlo, B * D / 4);
    split_kernel<<<(A * D / 4 + 255) / 256, 256>>>(anchors, ahi, alo, A * D / 4);
    trans_split_kernel<<<dim3(H / 32, D / 32), dim3(32, 8)>>>(Wq, Wqthi, Wqtlo, D, H);
    trans_split_kernel<<<dim3(H / 32, D / 32), dim3(32, 8)>>>(Wk, Wkthi, Wktlo, D, H);
    trans_half_kernel<<<dim3(H / 32, A / 32), dim3(32, 8)>>>(values, Vt, A, H);

    // 2) projections (3-term bf16 mma, fp32 store)
    proj3_kernel<<<dim3(H / 128, B / 128), 256, SMEM4>>>(
        xhi, xlo, Wqthi, Wqtlo, D, H, Qf);
    proj3_kernel<<<dim3(H / 128, A / 128), 256, SMEM4>>>(
        ahi, alo, Wkthi, Wktlo, D, H, Kf);

    // 3) l2 normalize: Q -> fp16 hi/lo of 1024*qhat (+den=0), K -> fp16
    l2norm_split_h_kernel<<<B, 128>>>(Qf, Qhi, Qlo, dn);
    l2norm_h_kernel<<<A, 128>>>(Kf, Kh);

    // 4) SIM: E = exp(quant((Qn @ Kn^T))) fp16, den = rowsum (2-term fp16)
    sim2_kernel<<<dim3(A / 128, B / 128), 256, SMEM3T>>>(
        Qhi, Qlo, Kh, H, A, dn, E);

    // 5) OUT: out = (E @ V) / den  (1-term fp16)
    out1_kernel<<<dim3(H / 128, B / 128), 256, SMEM2T>>>(
        E, Vt, A, H, dn, out);
}